// round 1
// baseline (speedup 1.0000x reference)
#include <cuda_runtime.h>

// ---------------- scratch (device globals; no allocation) ----------------
__device__ __align__(16) float g_h1[64*18*28*28];   // dw1 out   [64,18,28,28]
__device__ __align__(16) float g_h2[64*51*14*14];   // pool1 out [64,51,14,14]
__device__ __align__(16) float g_h3[64*255*10*10];  // dw2 out   [64,255,10,10]
__device__ __align__(16) float g_h4[64*515*25];     // pool2 out [64,515,5,5]
__device__ __align__(16) float g_h5[64*100*25];     // oo out    [64,100,5,5]
__device__ __align__(16) float g_wpad[100*520];     // padded oo_w

// ---------------- prep: pad oo_w [100,515] -> [100,520] ----------------
__global__ void k_prep(const float* __restrict__ oo_w) {
    int idx = blockIdx.x*blockDim.x + threadIdx.x;
    if (idx >= 100*520) return;
    int o = idx / 520, c = idx % 520;
    g_wpad[idx] = (c < 515) ? oo_w[o*515 + c] : 0.f;
}

// ---------------- dw1: [64,3,32,32] -> [64,18,28,28], groups=3 ----------------
__global__ void k_dw1(const float* __restrict__ x, const float* __restrict__ w,
                      const float* __restrict__ bias) {
    int idx = blockIdx.x*blockDim.x + threadIdx.x;
    const int N = 64*18*28*28;
    if (idx >= N) return;
    int px = idx % 28, t = idx / 28;
    int py = t % 28; t /= 28;
    int o = t % 18; int b = t / 18;
    int c = o / 6;
    const float* xp = x + (((size_t)b*3 + c)*32 + py)*32 + px;
    const float* wp = w + o*25;
    float acc = bias[o];
    #pragma unroll
    for (int dy = 0; dy < 5; dy++)
        #pragma unroll
        for (int dx = 0; dx < 5; dx++)
            acc = fmaf(xp[dy*32+dx], wp[dy*5+dx], acc);
    g_h1[idx] = acc;
}

// ---------------- pc1 + relu + maxpool: [64,18,28,28] -> [64,51,14,14] ----------------
__global__ void k_pc1(const float* __restrict__ pw, const float* __restrict__ pb) {
    int idx = blockIdx.x*blockDim.x + threadIdx.x;
    const int N = 64*51*14*14;
    if (idx >= N) return;
    int qx = idx % 14, t = idx / 14;
    int qy = t % 14; t /= 14;
    int g = t % 51; int b = t / 51;
    // g -> (i,j,k), F=6, ncpf=3 (closed form of build_perm)
    int gi = g, i = 0;
    for (;;) { int cnt = (6 - i) + 2 * (5 - i); if (gi < cnt) break; gi -= cnt; i++; }
    int j, k;
    if (gi < 6 - i) { j = 0; k = i + gi; }
    else { gi -= 6 - i; int pj = 5 - i; j = 1 + gi / pj; k = i + 1 + gi % pj; }
    int s0 = (0==j) ? i*3+0 : k*3+0;
    int s1 = (1==j) ? i*3+1 : k*3+1;
    int s2 = (2==j) ? i*3+2 : k*3+2;
    float w0 = pw[g*3+0], w1 = pw[g*3+1], w2 = pw[g*3+2];
    const float* p0 = g_h1 + ((size_t)b*18+s0)*784;
    const float* p1 = g_h1 + ((size_t)b*18+s1)*784;
    const float* p2 = g_h1 + ((size_t)b*18+s2)*784;
    float m = -1e30f;
    #pragma unroll
    for (int dy = 0; dy < 2; dy++) {
        int y = 2*qy + dy;
        #pragma unroll
        for (int dx = 0; dx < 2; dx++) {
            int xx = 2*qx + dx;
            float v = fmaf(w0, p0[y*28+xx], fmaf(w1, p1[y*28+xx], w2*p2[y*28+xx]));
            m = fmaxf(m, v);
        }
    }
    g_h2[idx] = fmaxf(m + pb[g], 0.f);
}

// ---------------- dw2: [64,51,14,14] -> [64,255,10,10], groups=51 ----------------
__global__ void k_dw2(const float* __restrict__ w, const float* __restrict__ bias) {
    int idx = blockIdx.x*blockDim.x + threadIdx.x;
    const int N = 64*255*10*10;
    if (idx >= N) return;
    int px = idx % 10, t = idx / 10;
    int py = t % 10; t /= 10;
    int o = t % 255; int b = t / 255;
    int c = o / 5;
    const float* ip = g_h2 + ((size_t)b*51 + c)*196;
    const float* wp = w + o*25;
    float acc = bias[o];
    #pragma unroll
    for (int dy = 0; dy < 5; dy++)
        #pragma unroll
        for (int dx = 0; dx < 5; dx++)
            acc = fmaf(ip[(py+dy)*14 + (px+dx)], wp[dy*5+dx], acc);
    g_h3[idx] = acc;
}

// ---------------- pc2 + relu + maxpool: [64,255,10,10] -> [64,515,5,5] ----------------
// Group (i,j,k) = filter-k channels with position j replaced by channel i*51+j.
// Y[g,p] = sum_c W[g,c]*X[k*51+c,p]  +  W[g,j]*(X[i*51+j,p] - X[k*51+j,p])
// Block = (b, chunk-of-groups sharing k). X tile (51x100) + W rows in smem.
__device__ __constant__ int c_bk[11]   = {0,1,2,2,3,3,3,4,4,4,4};
__device__ __constant__ int c_bt[11]   = {0,0,0,52,0,52,104,0,52,104,156};
__device__ __constant__ int c_bc[11]   = {1,52,52,51,52,52,50,52,52,52,49};
__device__ __constant__ int c_base[5]  = {0,205,359,462,514};

__global__ void k_pc2(const float* __restrict__ pw, const float* __restrict__ pb) {
    __shared__ __align__(16) float Xs[5100];      // 51 ch x 100 pos
    __shared__ __align__(16) float Ws[52*51];
    __shared__ int   s_g[52];
    __shared__ int   s_cc[52];
    __shared__ int   s_j[52];
    __shared__ float s_b[52];
    int blk = blockIdx.x;            // 0..10
    int b   = blockIdx.y;            // 0..63
    int k   = c_bk[blk], ts = c_bt[blk], cnt = c_bc[blk];
    int tid = threadIdx.x;

    const float* xsrc = g_h3 + ((size_t)b*255 + k*51)*100;
    for (int t = tid; t < 5100; t += 256) Xs[t] = xsrc[t];

    if (tid < cnt) {
        int t = ts + tid;
        int i, j;
        if (t <= k) { i = t; j = 0; }
        else { int r = t - k - 1; i = r % k; j = 1 + r / k; }
        int g;
        if (j == 0) g = c_base[i] + (k - i);
        else        g = c_base[i] + (5 - i) + (j - 1)*(4 - i) + (k - i - 1);
        s_g[tid] = g; s_cc[tid] = i*51 + j; s_j[tid] = j; s_b[tid] = pb[g];
    }
    __syncthreads();
    for (int t = tid; t < cnt*51; t += 256) {
        int tl = t / 51, c = t % 51;
        Ws[t] = pw[s_g[tl]*51 + c];
    }
    __syncthreads();

    int ntask = cnt * 5;                       // (group, pooled-row)
    for (int task = tid; task < ntask; task += 256) {
        int tl = task / 5, ph = task % 5;
        int y0 = 2*ph, y1 = y0 + 1;
        float r0[10], r1[10];
        #pragma unroll
        for (int xx = 0; xx < 10; xx++) { r0[xx] = 0.f; r1[xx] = 0.f; }
        const float* wrow = &Ws[tl*51];
        #pragma unroll 3
        for (int c = 0; c < 51; c++) {
            float wc = wrow[c];
            const float2* a0 = (const float2*)&Xs[c*100 + y0*10];
            const float2* a1 = (const float2*)&Xs[c*100 + y1*10];
            #pragma unroll
            for (int x2 = 0; x2 < 5; x2++) {
                float2 v0 = a0[x2], v1 = a1[x2];
                r0[2*x2]   = fmaf(wc, v0.x, r0[2*x2]);
                r0[2*x2+1] = fmaf(wc, v0.y, r0[2*x2+1]);
                r1[2*x2]   = fmaf(wc, v1.x, r1[2*x2]);
                r1[2*x2+1] = fmaf(wc, v1.y, r1[2*x2+1]);
            }
        }
        // correction: replace channel k*51+j by i*51+j
        int jj = s_j[tl];
        float wj = wrow[jj];
        const float* gsrc = g_h3 + ((size_t)b*255 + s_cc[tl])*100;
        #pragma unroll
        for (int xx = 0; xx < 10; xx++) {
            r0[xx] = fmaf(wj, gsrc[y0*10+xx] - Xs[jj*100 + y0*10 + xx], r0[xx]);
            r1[xx] = fmaf(wj, gsrc[y1*10+xx] - Xs[jj*100 + y1*10 + xx], r1[xx]);
        }
        float bias = s_b[tl];
        float* outp = g_h4 + ((size_t)b*515 + s_g[tl])*25 + ph*5;
        #pragma unroll
        for (int pp = 0; pp < 5; pp++) {
            float v = fmaxf(fmaxf(r0[2*pp], r0[2*pp+1]), fmaxf(r1[2*pp], r1[2*pp+1]));
            outp[pp] = fmaxf(v + bias, 0.f);
        }
    }
}

// ---------------- oo (1x1, 515->100) + relu: [64,515,25] -> [64,100,25] ----------------
__global__ void k_oo(const float* __restrict__ ob) {
    __shared__ __align__(16) float Xs[260*25];
    int b = blockIdx.y;
    int obase = blockIdx.x * 50;     // 2 halves of o
    int tid = threadIdx.x;
    float acc[5] = {0,0,0,0,0};
    int oo_[5], pp_[5], nt = 0;
    for (int task = tid; task < 1250; task += 256) { oo_[nt] = obase + task/25; pp_[nt] = task%25; nt++; }
    #pragma unroll
    for (int chunk = 0; chunk < 2; chunk++) {
        int c0 = chunk * 260;
        int cn = (chunk == 0) ? 260 : 256;   // 516 padded channels total
        __syncthreads();
        for (int t = tid; t < cn*25; t += 256) {
            int cc = t / 25, p = t % 25;
            int ch = c0 + cc;
            Xs[t] = (ch < 515) ? g_h4[((size_t)b*515 + ch)*25 + p] : 0.f;
        }
        __syncthreads();
        for (int s = 0; s < nt; s++) {
            int o = oo_[s], p = pp_[s];
            const float4* wp = (const float4*)&g_wpad[o*520 + c0];
            float a = acc[s];
            for (int c4 = 0; c4 < cn/4; c4++) {
                float4 w4 = wp[c4];
                const float* xp = &Xs[(c4*4)*25 + p];
                a = fmaf(w4.x, xp[0],  a);
                a = fmaf(w4.y, xp[25], a);
                a = fmaf(w4.z, xp[50], a);
                a = fmaf(w4.w, xp[75], a);
            }
            acc[s] = a;
        }
    }
    for (int s = 0; s < nt; s++) {
        int o = oo_[s], p = pp_[s];
        g_h5[((size_t)b*100 + o)*25 + p] = fmaxf(acc[s] + ob[o], 0.f);
    }
}

// ---------------- fused FCs: [64,2500] -> 120 -> 84 -> 10 ----------------
__global__ void k_fc(const float* __restrict__ w1, const float* __restrict__ b1,
                     const float* __restrict__ w2, const float* __restrict__ b2,
                     const float* __restrict__ w3, const float* __restrict__ b3,
                     float* __restrict__ out) {
    __shared__ __align__(16) float sx[2500];
    __shared__ __align__(16) float f1[120];
    __shared__ __align__(16) float f2[84];
    int b = blockIdx.x, tid = threadIdx.x;
    const float4* xsrc = (const float4*)(g_h5 + (size_t)b*2500);
    float4* sx4 = (float4*)sx;
    for (int t = tid; t < 625; t += 256) sx4[t] = xsrc[t];
    __syncthreads();
    int warp = tid >> 5, lane = tid & 31;
    for (int o = warp; o < 120; o += 8) {
        const float4* wp = (const float4*)(w1 + (size_t)o*2500);
        float s = 0.f;
        for (int idx = lane; idx < 625; idx += 32) {
            float4 wv = wp[idx], xv = sx4[idx];
            s = fmaf(wv.x, xv.x, s); s = fmaf(wv.y, xv.y, s);
            s = fmaf(wv.z, xv.z, s); s = fmaf(wv.w, xv.w, s);
        }
        #pragma unroll
        for (int off = 16; off > 0; off >>= 1) s += __shfl_down_sync(0xffffffffu, s, off);
        if (lane == 0) f1[o] = fmaxf(s + b1[o], 0.f);
    }
    __syncthreads();
    if (tid < 84) {
        const float4* wp = (const float4*)(w2 + tid*120);
        const float4* xp = (const float4*)f1;
        float s = 0.f;
        #pragma unroll
        for (int q = 0; q < 30; q++) {
            float4 wv = wp[q], xv = xp[q];
            s = fmaf(wv.x,xv.x,s); s = fmaf(wv.y,xv.y,s);
            s = fmaf(wv.z,xv.z,s); s = fmaf(wv.w,xv.w,s);
        }
        f2[tid] = fmaxf(s + b2[tid], 0.f);
    }
    __syncthreads();
    if (tid < 10) {
        const float4* wp = (const float4*)(w3 + tid*84);
        const float4* xp = (const float4*)f2;
        float s = 0.f;
        #pragma unroll
        for (int q = 0; q < 21; q++) {
            float4 wv = wp[q], xv = xp[q];
            s = fmaf(wv.x,xv.x,s); s = fmaf(wv.y,xv.y,s);
            s = fmaf(wv.z,xv.z,s); s = fmaf(wv.w,xv.w,s);
        }
        out[b*10 + tid] = s + b3[tid];
    }
}

// ---------------- launch ----------------
extern "C" void kernel_launch(void* const* d_in, const int* in_sizes, int n_in,
                              void* d_out, int out_size) {
    const float* x      = (const float*)d_in[0];
    const float* dw1_w  = (const float*)d_in[1];
    const float* dw1_b  = (const float*)d_in[2];
    const float* pc1_w  = (const float*)d_in[3];
    const float* pc1_b  = (const float*)d_in[4];
    const float* dw2_w  = (const float*)d_in[5];
    const float* dw2_b  = (const float*)d_in[6];
    const float* pc2_w  = (const float*)d_in[7];
    const float* pc2_b  = (const float*)d_in[8];
    const float* oo_w   = (const float*)d_in[9];
    const float* oo_b   = (const float*)d_in[10];
    const float* fc1_w  = (const float*)d_in[11];
    const float* fc1_b  = (const float*)d_in[12];
    const float* fc2_w  = (const float*)d_in[13];
    const float* fc2_b  = (const float*)d_in[14];
    const float* fc3_w  = (const float*)d_in[15];
    const float* fc3_b  = (const float*)d_in[16];
    float* out = (float*)d_out;

    k_prep<<<(100*520 + 255)/256, 256>>>(oo_w);
    k_dw1<<<(64*18*28*28 + 255)/256, 256>>>(x, dw1_w, dw1_b);
    k_pc1<<<(64*51*14*14 + 255)/256, 256>>>(pc1_w, pc1_b);
    k_dw2<<<(64*255*10*10 + 255)/256, 256>>>(dw2_w, dw2_b);
    k_pc2<<<dim3(11, 64), 256>>>(pc2_w, pc2_b);
    k_oo<<<dim3(2, 64), 256>>>(oo_b);
    k_fc<<<64, 256>>>(fc1_w, fc1_b, fc2_w, fc2_b, fc3_w, fc3_b, out);
}

// round 2
// speedup vs baseline: 1.2173x; 1.2173x over previous
#include <cuda_runtime.h>

// ---------------- scratch (device globals; no allocation) ----------------
__device__ __align__(16) float g_h2[64*51*14*14];   // pool1 out [64,51,14,14]
__device__ __align__(16) float g_h3[64*255*10*10];  // dw2 out   [64,255,10,10]
__device__ __align__(16) float g_h4[64*515*25];     // pool2 out [64,515,5,5]
__device__ __align__(16) float g_h5[64*100*25];     // oo out    [64,100,5,5]

// =======================================================================
// fuse1: dw1 + pc1 + relu + maxpool, one block per batch image.
// x[b]: 3x32x32 -> smem (row pad 33). dw1 -> h1 smem (18x784).
// pc1 (perm closed-form) + pool -> g_h2 [64,51,14,14].
// =======================================================================
__global__ __launch_bounds__(256) void k_fuse1(
    const float* __restrict__ x, const float* __restrict__ dw1w,
    const float* __restrict__ dw1b, const float* __restrict__ pc1w,
    const float* __restrict__ pc1b) {
    extern __shared__ float sm[];
    float* xs  = sm;            // 3*32*33 = 3168
    float* h1  = xs + 3168;     // 18*784 = 14112
    float* ws  = h1 + 14112;    // 450
    float* wb  = ws + 450;      // 18
    float* pwv = wb + 18;       // 153
    float* pbs = pwv + 153;     // 51
    int*   sidx = (int*)(pbs + 51); // 51*3

    int b = blockIdx.x, tid = threadIdx.x;

    for (int i = tid; i < 3072; i += 256) {
        int c = i >> 10, r = (i >> 5) & 31, col = i & 31;
        xs[c*1056 + r*33 + col] = x[(size_t)b*3072 + i];
    }
    for (int i = tid; i < 450; i += 256) ws[i] = dw1w[i];
    if (tid < 18) wb[tid] = dw1b[tid];
    for (int i = tid; i < 153; i += 256) pwv[i] = pc1w[i];
    if (tid < 51) {
        pbs[tid] = pc1b[tid];
        int g = tid, gi = g, i = 0;
        for (;;) { int cv = (6 - i) + 2 * (5 - i); if (gi < cv) break; gi -= cv; i++; }
        int j, k;
        if (gi < 6 - i) { j = 0; k = i + gi; }
        else { gi -= 6 - i; int pj = 5 - i; j = 1 + gi / pj; k = i + 1 + gi % pj; }
        sidx[g*3+0] = (0==j) ? i*3+0 : k*3+0;
        sidx[g*3+1] = (1==j) ? i*3+1 : k*3+1;
        sidx[g*3+2] = (2==j) ? i*3+2 : k*3+2;
    }
    __syncthreads();

    // dw1: tasks = (o, py, quarter) = 18*28*4 = 2016; each computes 7 px.
    for (int t = tid; t < 2016; t += 256) {
        int o = t / 112, r = t % 112, py = r / 4, q = r % 4, x0 = q * 7;
        int c = o / 6;
        const float* xb = &xs[c*1056 + py*33 + x0];
        float win[5][11];
        #pragma unroll
        for (int dy = 0; dy < 5; dy++)
            #pragma unroll
            for (int dx = 0; dx < 11; dx++) win[dy][dx] = xb[dy*33 + dx];
        float bv = wb[o];
        float acc[7];
        #pragma unroll
        for (int u = 0; u < 7; u++) acc[u] = bv;
        #pragma unroll
        for (int dy = 0; dy < 5; dy++)
            #pragma unroll
            for (int dx = 0; dx < 5; dx++) {
                float wv = ws[o*25 + dy*5 + dx];
                #pragma unroll
                for (int u = 0; u < 7; u++) acc[u] = fmaf(win[dy][dx+u], wv, acc[u]);
            }
        #pragma unroll
        for (int u = 0; u < 7; u++) h1[o*784 + py*28 + x0 + u] = acc[u];
    }
    __syncthreads();

    // pc1 + pool: tasks = (g, qy, qp) = 51*14*7 = 4998; each -> 2 pooled outputs.
    for (int t = tid; t < 4998; t += 256) {
        int g = t / 98, r = t % 98, qy = r / 7, qp = r % 7;
        float w0 = pwv[g*3], w1 = pwv[g*3+1], w2 = pwv[g*3+2];
        int s0 = sidx[g*3], s1 = sidx[g*3+1], s2 = sidx[g*3+2];
        float v[2][4];
        #pragma unroll
        for (int dy = 0; dy < 2; dy++) {
            int base = (2*qy + dy)*28 + 4*qp;
            float2 a0 = *(const float2*)&h1[s0*784 + base];
            float2 a0b = *(const float2*)&h1[s0*784 + base + 2];
            float2 a1 = *(const float2*)&h1[s1*784 + base];
            float2 a1b = *(const float2*)&h1[s1*784 + base + 2];
            float2 a2 = *(const float2*)&h1[s2*784 + base];
            float2 a2b = *(const float2*)&h1[s2*784 + base + 2];
            v[dy][0] = fmaf(w0, a0.x,  fmaf(w1, a1.x,  w2*a2.x));
            v[dy][1] = fmaf(w0, a0.y,  fmaf(w1, a1.y,  w2*a2.y));
            v[dy][2] = fmaf(w0, a0b.x, fmaf(w1, a1b.x, w2*a2b.x));
            v[dy][3] = fmaf(w0, a0b.y, fmaf(w1, a1b.y, w2*a2b.y));
        }
        float bv = pbs[g];
        float o0 = fmaxf(fmaxf(v[0][0], v[0][1]), fmaxf(v[1][0], v[1][1]));
        float o1 = fmaxf(fmaxf(v[0][2], v[0][3]), fmaxf(v[1][2], v[1][3]));
        float* op = &g_h2[((size_t)b*51 + g)*196 + qy*14 + 2*qp];
        op[0] = fmaxf(o0 + bv, 0.f);
        op[1] = fmaxf(o1 + bv, 0.f);
    }
}

// =======================================================================
// dw2: [64,51,14,14] -> [64,255,10,10]. Block = (bx 0..9, b). Task = (o, py),
// thread computes a full 10-wide output row in two 5-wide register chunks.
// =======================================================================
__global__ __launch_bounds__(256) void k_dw2(const float* __restrict__ w,
                                             const float* __restrict__ bias) {
    __shared__ float xs[7*196];
    int bx = blockIdx.x, b = blockIdx.y, tid = threadIdx.x;
    int t0 = bx * 256;
    int c0 = t0 / 50;
    int c1 = min((t0 + 255) / 50, 50);
    int nch = c1 - c0 + 1;
    for (int i = tid; i < nch*196; i += 256)
        xs[i] = g_h2[((size_t)b*51 + c0)*196 + i];
    __syncthreads();

    int t = t0 + tid;
    if (t >= 2550) return;
    int o = t / 10, py = t % 10;
    int cl = o / 5 - c0;
    float wr[25];
    #pragma unroll
    for (int i = 0; i < 25; i++) wr[i] = __ldg(&w[o*25 + i]);
    float bv = __ldg(&bias[o]);
    const float* ib = &xs[cl*196 + py*14];
    float* outp = &g_h3[((size_t)b*255 + o)*100 + py*10];
    #pragma unroll
    for (int h = 0; h < 2; h++) {
        int px0 = h * 5;
        float win[5][9];
        #pragma unroll
        for (int dy = 0; dy < 5; dy++)
            #pragma unroll
            for (int dx = 0; dx < 9; dx++) win[dy][dx] = ib[dy*14 + px0 + dx];
        float acc[5] = {bv, bv, bv, bv, bv};
        #pragma unroll
        for (int dy = 0; dy < 5; dy++)
            #pragma unroll
            for (int dx = 0; dx < 5; dx++) {
                float wv = wr[dy*5 + dx];
                #pragma unroll
                for (int u = 0; u < 5; u++) acc[u] = fmaf(win[dy][dx+u], wv, acc[u]);
            }
        #pragma unroll
        for (int u = 0; u < 5; u++) outp[px0 + u] = acc[u];
    }
}

// =======================================================================
// pc2 + relu + maxpool. Block = (kblk 0..10, b). Register tile:
// thread = (group-pair, pooled-row) -> 2 groups x 20 positions.
// Y[g,p] = sum_c W[g,c]*X[k*51+c,p] + W[g,j]*(X[i*51+j,p]-X[k*51+j,p])
// =======================================================================
__device__ __constant__ int c_bk[11]   = {0,1,2,2,3,3,3,4,4,4,4};
__device__ __constant__ int c_bt[11]   = {0,0,0,52,0,52,104,0,52,104,156};
__device__ __constant__ int c_bc[11]   = {1,52,52,51,52,52,50,52,52,52,49};
__device__ __constant__ int c_base[5]  = {0,205,359,462,514};

__global__ __launch_bounds__(160) void k_pc2(const float* __restrict__ pw,
                                             const float* __restrict__ pb) {
    __shared__ __align__(16) float Xs[5100];     // 51 ch x 100 pos
    __shared__ __align__(16) float Wt[51*52];    // transposed: Wt[c*52+l]
    __shared__ int   s_g[52], s_cc[52], s_j[52];
    __shared__ float s_b[52];
    int blk = blockIdx.x, b = blockIdx.y, tid = threadIdx.x;
    int k = c_bk[blk], ts = c_bt[blk], cnt = c_bc[blk];

    const float* xsrc = g_h3 + ((size_t)b*255 + k*51)*100;
    for (int i = tid; i < 5100; i += 160) Xs[i] = xsrc[i];
    if (tid < cnt) {
        int t = ts + tid;
        int i, j;
        if (t <= k) { i = t; j = 0; }
        else { int r = t - k - 1; i = r % k; j = 1 + r / k; }
        int g;
        if (j == 0) g = c_base[i] + (k - i);
        else        g = c_base[i] + (5 - i) + (j - 1)*(4 - i) + (k - i - 1);
        s_g[tid] = g; s_cc[tid] = i*51 + j; s_j[tid] = j; s_b[tid] = pb[g];
    }
    __syncthreads();
    for (int i = tid; i < cnt*51; i += 160) {
        int l = i / 51, c = i % 51;
        Wt[c*52 + l] = pw[s_g[l]*51 + c];
    }
    __syncthreads();

    int gt = tid / 5, rp = tid % 5;
    int l0 = gt * 2;
    if (tid >= 130 || l0 >= cnt) return;
    bool v1 = (l0 + 1 < cnt);
    int y0 = 2 * rp;

    float a0[20], a1[20];
    #pragma unroll
    for (int u = 0; u < 20; u++) { a0[u] = 0.f; a1[u] = 0.f; }

    #pragma unroll 3
    for (int c = 0; c < 51; c++) {
        float2 wp2 = *(const float2*)&Wt[c*52 + l0];
        const float4* xr = (const float4*)&Xs[c*100 + y0*10];
        #pragma unroll
        for (int q = 0; q < 5; q++) {
            float4 xv = xr[q];
            a0[4*q+0] = fmaf(wp2.x, xv.x, a0[4*q+0]);
            a0[4*q+1] = fmaf(wp2.x, xv.y, a0[4*q+1]);
            a0[4*q+2] = fmaf(wp2.x, xv.z, a0[4*q+2]);
            a0[4*q+3] = fmaf(wp2.x, xv.w, a0[4*q+3]);
            a1[4*q+0] = fmaf(wp2.y, xv.x, a1[4*q+0]);
            a1[4*q+1] = fmaf(wp2.y, xv.y, a1[4*q+1]);
            a1[4*q+2] = fmaf(wp2.y, xv.z, a1[4*q+2]);
            a1[4*q+3] = fmaf(wp2.y, xv.w, a1[4*q+3]);
        }
    }

    // corrections + pool + store, per group
    #pragma unroll
    for (int s = 0; s < 2; s++) {
        if (s == 1 && !v1) break;
        int l = l0 + s;
        float* a = (s == 0) ? a0 : a1;
        int jj = s_j[l], cc = s_cc[l];
        float wj = Wt[jj*52 + l];
        const float* gs = g_h3 + ((size_t)b*255 + cc)*100 + y0*10;
        const float* xj = &Xs[jj*100 + y0*10];
        #pragma unroll
        for (int u = 0; u < 20; u++)
            a[u] = fmaf(wj, gs[u] - xj[u], a[u]);
        float bv = s_b[l];
        float* op = &g_h4[((size_t)b*515 + s_g[l])*25 + rp*5];
        #pragma unroll
        for (int p = 0; p < 5; p++) {
            float v = fmaxf(fmaxf(a[2*p], a[2*p+1]), fmaxf(a[10+2*p], a[10+2*p+1]));
            op[p] = fmaxf(v + bv, 0.f);
        }
    }
}

// =======================================================================
// oo (1x1 conv 515->100) + relu. Block = (ohalf, b), 128 threads.
// Thread tile 2o x 5p; W streamed through double-buffered smem chunks.
// =======================================================================
__global__ __launch_bounds__(128) void k_oo(const float* __restrict__ ow,
                                            const float* __restrict__ ob) {
    extern __shared__ float sm[];
    float* Xs = sm;           // 12875 (+pad)
    float* Wb = Xs + 12880;   // 2 x 64*50 = 6400
    int half = blockIdx.x, b = blockIdx.y, tid = threadIdx.x;
    int obase = half * 50;

    for (int i = tid; i < 12875; i += 128)
        Xs[i] = g_h4[(size_t)b*12875 + i];

    const int CS = 64;
    const int NCH = 9;  // ceil(515/64)
    // stage chunk 0
    {
        int csz = CS;
        float* W = Wb;
        for (int i = tid; i < 50*csz; i += 128) {
            int o = i / csz, cl = i % csz;
            W[cl*50 + o] = __ldg(&ow[(size_t)(obase + o)*515 + cl]);
        }
    }
    __syncthreads();

    int ot = tid / 5, pt = tid % 5;
    bool act = tid < 125;
    int o0 = ot * 2;
    int p0 = pt * 5;
    float acc[10];
    #pragma unroll
    for (int u = 0; u < 10; u++) acc[u] = 0.f;

    for (int ch = 0; ch < NCH; ch++) {
        int c0 = ch * CS;
        int csz = min(CS, 515 - c0);
        const float* W = Wb + (ch & 1) * 3200;
        if (ch + 1 < NCH) {
            int nc0 = c0 + CS;
            int ncsz = min(CS, 515 - nc0);
            float* Wn = Wb + ((ch + 1) & 1) * 3200;
            for (int i = tid; i < 50*ncsz; i += 128) {
                int o = i / ncsz, cl = i % ncsz;
                Wn[cl*50 + o] = __ldg(&ow[(size_t)(obase + o)*515 + nc0 + cl]);
            }
        }
        if (act) {
            #pragma unroll 4
            for (int cl = 0; cl < csz; cl++) {
                float2 wv = *(const float2*)&W[cl*50 + o0];
                const float* xp = &Xs[(c0 + cl)*25 + p0];
                #pragma unroll
                for (int u = 0; u < 5; u++) {
                    float xv = xp[u];
                    acc[u]     = fmaf(wv.x, xv, acc[u]);
                    acc[5 + u] = fmaf(wv.y, xv, acc[5 + u]);
                }
            }
        }
        __syncthreads();
    }

    if (act) {
        int og = obase + o0;
        float b0 = __ldg(&ob[og]), b1 = __ldg(&ob[og + 1]);
        float* op0 = &g_h5[((size_t)b*100 + og)*25 + p0];
        float* op1 = op0 + 25;
        #pragma unroll
        for (int u = 0; u < 5; u++) {
            op0[u] = fmaxf(acc[u]     + b0, 0.f);
            op1[u] = fmaxf(acc[5 + u] + b1, 0.f);
        }
    }
}

// =======================================================================
// fused FCs: [64,2500] -> 120 -> 84 -> 10
// =======================================================================
__global__ __launch_bounds__(256) void k_fc(
    const float* __restrict__ w1, const float* __restrict__ b1,
    const float* __restrict__ w2, const float* __restrict__ b2,
    const float* __restrict__ w3, const float* __restrict__ b3,
    float* __restrict__ out) {
    __shared__ __align__(16) float sx[2500];
    __shared__ __align__(16) float f1[120];
    __shared__ __align__(16) float f2[84];
    int b = blockIdx.x, tid = threadIdx.x;
    const float4* xsrc = (const float4*)(g_h5 + (size_t)b*2500);
    float4* sx4 = (float4*)sx;
    for (int t = tid; t < 625; t += 256) sx4[t] = xsrc[t];
    __syncthreads();
    int warp = tid >> 5, lane = tid & 31;
    for (int o = warp; o < 120; o += 8) {
        const float4* wp = (const float4*)(w1 + (size_t)o*2500);
        float s = 0.f;
        for (int idx = lane; idx < 625; idx += 32) {
            float4 wv = wp[idx], xv = sx4[idx];
            s = fmaf(wv.x, xv.x, s); s = fmaf(wv.y, xv.y, s);
            s = fmaf(wv.z, xv.z, s); s = fmaf(wv.w, xv.w, s);
        }
        #pragma unroll
        for (int off = 16; off > 0; off >>= 1) s += __shfl_down_sync(0xffffffffu, s, off);
        if (lane == 0) f1[o] = fmaxf(s + b1[o], 0.f);
    }
    __syncthreads();
    if (tid < 84) {
        const float4* wp = (const float4*)(w2 + tid*120);
        const float4* xp = (const float4*)f1;
        float s = 0.f;
        #pragma unroll
        for (int q = 0; q < 30; q++) {
            float4 wv = wp[q], xv = xp[q];
            s = fmaf(wv.x, xv.x, s); s = fmaf(wv.y, xv.y, s);
            s = fmaf(wv.z, xv.z, s); s = fmaf(wv.w, xv.w, s);
        }
        f2[tid] = fmaxf(s + b2[tid], 0.f);
    }
    __syncthreads();
    if (tid < 10) {
        const float4* wp = (const float4*)(w3 + tid*84);
        const float4* xp = (const float4*)f2;
        float s = 0.f;
        #pragma unroll
        for (int q = 0; q < 21; q++) {
            float4 wv = wp[q], xv = xp[q];
            s = fmaf(wv.x, xv.x, s); s = fmaf(wv.y, xv.y, s);
            s = fmaf(wv.z, xv.z, s); s = fmaf(wv.w, xv.w, s);
        }
        out[b*10 + tid] = s + b3[tid];
    }
}

// ---------------- launch ----------------
extern "C" void kernel_launch(void* const* d_in, const int* in_sizes, int n_in,
                              void* d_out, int out_size) {
    const float* x      = (const float*)d_in[0];
    const float* dw1_w  = (const float*)d_in[1];
    const float* dw1_b  = (const float*)d_in[2];
    const float* pc1_w  = (const float*)d_in[3];
    const float* pc1_b  = (const float*)d_in[4];
    const float* dw2_w  = (const float*)d_in[5];
    const float* dw2_b  = (const float*)d_in[6];
    const float* pc2_w  = (const float*)d_in[7];
    const float* pc2_b  = (const float*)d_in[8];
    const float* oo_w   = (const float*)d_in[9];
    const float* oo_b   = (const float*)d_in[10];
    const float* fc1_w  = (const float*)d_in[11];
    const float* fc1_b  = (const float*)d_in[12];
    const float* fc2_w  = (const float*)d_in[13];
    const float* fc2_b  = (const float*)d_in[14];
    const float* fc3_w  = (const float*)d_in[15];
    const float* fc3_b  = (const float*)d_in[16];
    float* out = (float*)d_out;

    static bool attr_done = false;
    const int fuse1_smem = (3168 + 14112 + 450 + 18 + 153 + 51 + 153) * 4 + 16;
    const int oo_smem    = (12880 + 6400) * 4;
    if (!attr_done) {
        cudaFuncSetAttribute(k_fuse1, cudaFuncAttributeMaxDynamicSharedMemorySize, fuse1_smem);
        cudaFuncSetAttribute(k_oo,    cudaFuncAttributeMaxDynamicSharedMemorySize, oo_smem);
        attr_done = true;
    }

    k_fuse1<<<64, 256, fuse1_smem>>>(x, dw1_w, dw1_b, pc1_w, pc1_b);
    k_dw2<<<dim3(10, 64), 256>>>(dw2_w, dw2_b);
    k_pc2<<<dim3(11, 64), 160>>>(pc2_w, pc2_b);
    k_oo<<<dim3(2, 64), 128, oo_smem>>>(oo_w, oo_b);
    k_fc<<<64, 256>>>(fc1_w, fc1_b, fc2_w, fc2_b, fc3_w, fc3_b, out);
}

// round 3
// speedup vs baseline: 2.0000x; 1.6430x over previous
#include <cuda_runtime.h>

// ---------------- scratch (device globals; no allocation) ----------------
__device__ __align__(16) float g_h2[64*51*14*14];    // pool1 out [64,51,14,14]
__device__ __align__(16) float g_h3[64*255*10*10];   // dw2 out   [64,255,10,10]
__device__ __align__(16) float g_h4[64*515*25];      // pool2 out [64,515,5,5]
__device__ __align__(16) float g_part[4*64*100*25];  // oo split-K partials
__device__ __align__(16) float g_h5[64*100*25];      // oo out (post relu)
__device__ __align__(16) float g_f1[64*120];         // fc1 out

// =======================================================================
// fuse1: dw1 + pc1 + relu + maxpool, one block per batch image.
// =======================================================================
__global__ __launch_bounds__(256) void k_fuse1(
    const float* __restrict__ x, const float* __restrict__ dw1w,
    const float* __restrict__ dw1b, const float* __restrict__ pc1w,
    const float* __restrict__ pc1b) {
    extern __shared__ float sm[];
    float* xs  = sm;            // 3*32*33 = 3168
    float* h1  = xs + 3168;     // 18*784 = 14112
    float* ws  = h1 + 14112;    // 450
    float* wb  = ws + 450;      // 18
    float* pwv = wb + 18;       // 153
    float* pbs = pwv + 153;     // 51
    int*   sidx = (int*)(pbs + 51); // 51*3

    int b = blockIdx.x, tid = threadIdx.x;

    for (int i = tid; i < 3072; i += 256) {
        int c = i >> 10, r = (i >> 5) & 31, col = i & 31;
        xs[c*1056 + r*33 + col] = x[(size_t)b*3072 + i];
    }
    for (int i = tid; i < 450; i += 256) ws[i] = dw1w[i];
    if (tid < 18) wb[tid] = dw1b[tid];
    for (int i = tid; i < 153; i += 256) pwv[i] = pc1w[i];
    if (tid < 51) {
        pbs[tid] = pc1b[tid];
        int g = tid, gi = g, i = 0;
        for (;;) { int cv = (6 - i) + 2 * (5 - i); if (gi < cv) break; gi -= cv; i++; }
        int j, k;
        if (gi < 6 - i) { j = 0; k = i + gi; }
        else { gi -= 6 - i; int pj = 5 - i; j = 1 + gi / pj; k = i + 1 + gi % pj; }
        sidx[g*3+0] = (0==j) ? i*3+0 : k*3+0;
        sidx[g*3+1] = (1==j) ? i*3+1 : k*3+1;
        sidx[g*3+2] = (2==j) ? i*3+2 : k*3+2;
    }
    __syncthreads();

    for (int t = tid; t < 2016; t += 256) {
        int o = t / 112, r = t % 112, py = r / 4, q = r % 4, x0 = q * 7;
        int c = o / 6;
        const float* xb = &xs[c*1056 + py*33 + x0];
        float win[5][11];
        #pragma unroll
        for (int dy = 0; dy < 5; dy++)
            #pragma unroll
            for (int dx = 0; dx < 11; dx++) win[dy][dx] = xb[dy*33 + dx];
        float bv = wb[o];
        float acc[7];
        #pragma unroll
        for (int u = 0; u < 7; u++) acc[u] = bv;
        #pragma unroll
        for (int dy = 0; dy < 5; dy++)
            #pragma unroll
            for (int dx = 0; dx < 5; dx++) {
                float wv = ws[o*25 + dy*5 + dx];
                #pragma unroll
                for (int u = 0; u < 7; u++) acc[u] = fmaf(win[dy][dx+u], wv, acc[u]);
            }
        #pragma unroll
        for (int u = 0; u < 7; u++) h1[o*784 + py*28 + x0 + u] = acc[u];
    }
    __syncthreads();

    for (int t = tid; t < 4998; t += 256) {
        int g = t / 98, r = t % 98, qy = r / 7, qp = r % 7;
        float w0 = pwv[g*3], w1 = pwv[g*3+1], w2 = pwv[g*3+2];
        int s0 = sidx[g*3], s1 = sidx[g*3+1], s2 = sidx[g*3+2];
        float v[2][4];
        #pragma unroll
        for (int dy = 0; dy < 2; dy++) {
            int base = (2*qy + dy)*28 + 4*qp;
            float2 a0 = *(const float2*)&h1[s0*784 + base];
            float2 a0b = *(const float2*)&h1[s0*784 + base + 2];
            float2 a1 = *(const float2*)&h1[s1*784 + base];
            float2 a1b = *(const float2*)&h1[s1*784 + base + 2];
            float2 a2 = *(const float2*)&h1[s2*784 + base];
            float2 a2b = *(const float2*)&h1[s2*784 + base + 2];
            v[dy][0] = fmaf(w0, a0.x,  fmaf(w1, a1.x,  w2*a2.x));
            v[dy][1] = fmaf(w0, a0.y,  fmaf(w1, a1.y,  w2*a2.y));
            v[dy][2] = fmaf(w0, a0b.x, fmaf(w1, a1b.x, w2*a2b.x));
            v[dy][3] = fmaf(w0, a0b.y, fmaf(w1, a1b.y, w2*a2b.y));
        }
        float bv = pbs[g];
        float o0 = fmaxf(fmaxf(v[0][0], v[0][1]), fmaxf(v[1][0], v[1][1]));
        float o1 = fmaxf(fmaxf(v[0][2], v[0][3]), fmaxf(v[1][2], v[1][3]));
        float* op = &g_h2[((size_t)b*51 + g)*196 + qy*14 + 2*qp];
        op[0] = fmaxf(o0 + bv, 0.f);
        op[1] = fmaxf(o1 + bv, 0.f);
    }
}

// =======================================================================
// dw2: [64,51,14,14] -> [64,255,10,10].
// =======================================================================
__global__ __launch_bounds__(256) void k_dw2(const float* __restrict__ w,
                                             const float* __restrict__ bias) {
    __shared__ float xs[7*196];
    int bx = blockIdx.x, b = blockIdx.y, tid = threadIdx.x;
    int t0 = bx * 256;
    int c0 = t0 / 50;
    int c1 = min((t0 + 255) / 50, 50);
    int nch = c1 - c0 + 1;
    for (int i = tid; i < nch*196; i += 256)
        xs[i] = g_h2[((size_t)b*51 + c0)*196 + i];
    __syncthreads();

    int t = t0 + tid;
    if (t >= 2550) return;
    int o = t / 10, py = t % 10;
    int cl = o / 5 - c0;
    float wr[25];
    #pragma unroll
    for (int i = 0; i < 25; i++) wr[i] = __ldg(&w[o*25 + i]);
    float bv = __ldg(&bias[o]);
    const float* ib = &xs[cl*196 + py*14];
    float* outp = &g_h3[((size_t)b*255 + o)*100 + py*10];
    #pragma unroll
    for (int h = 0; h < 2; h++) {
        int px0 = h * 5;
        float win[5][9];
        #pragma unroll
        for (int dy = 0; dy < 5; dy++)
            #pragma unroll
            for (int dx = 0; dx < 9; dx++) win[dy][dx] = ib[dy*14 + px0 + dx];
        float acc[5] = {bv, bv, bv, bv, bv};
        #pragma unroll
        for (int dy = 0; dy < 5; dy++)
            #pragma unroll
            for (int dx = 0; dx < 5; dx++) {
                float wv = wr[dy*5 + dx];
                #pragma unroll
                for (int u = 0; u < 5; u++) acc[u] = fmaf(win[dy][dx+u], wv, acc[u]);
            }
        #pragma unroll
        for (int u = 0; u < 5; u++) outp[px0 + u] = acc[u];
    }
}

// =======================================================================
// pc2 + relu + maxpool.
// =======================================================================
__device__ __constant__ int c_bk[11]   = {0,1,2,2,3,3,3,4,4,4,4};
__device__ __constant__ int c_bt[11]   = {0,0,0,52,0,52,104,0,52,104,156};
__device__ __constant__ int c_bc[11]   = {1,52,52,51,52,52,50,52,52,52,49};
__device__ __constant__ int c_base[5]  = {0,205,359,462,514};

__global__ __launch_bounds__(160) void k_pc2(const float* __restrict__ pw,
                                             const float* __restrict__ pb) {
    __shared__ __align__(16) float Xs[5100];
    __shared__ __align__(16) float Wt[51*52];
    __shared__ int   s_g[52], s_cc[52], s_j[52];
    __shared__ float s_b[52];
    int blk = blockIdx.x, b = blockIdx.y, tid = threadIdx.x;
    int k = c_bk[blk], ts = c_bt[blk], cnt = c_bc[blk];

    const float* xsrc = g_h3 + ((size_t)b*255 + k*51)*100;
    for (int i = tid; i < 5100; i += 160) Xs[i] = xsrc[i];
    if (tid < cnt) {
        int t = ts + tid;
        int i, j;
        if (t <= k) { i = t; j = 0; }
        else { int r = t - k - 1; i = r % k; j = 1 + r / k; }
        int g;
        if (j == 0) g = c_base[i] + (k - i);
        else        g = c_base[i] + (5 - i) + (j - 1)*(4 - i) + (k - i - 1);
        s_g[tid] = g; s_cc[tid] = i*51 + j; s_j[tid] = j; s_b[tid] = pb[g];
    }
    __syncthreads();
    for (int i = tid; i < cnt*51; i += 160) {
        int l = i / 51, c = i % 51;
        Wt[c*52 + l] = pw[s_g[l]*51 + c];
    }
    __syncthreads();

    int gt = tid / 5, rp = tid % 5;
    int l0 = gt * 2;
    if (tid >= 130 || l0 >= cnt) return;
    bool v1 = (l0 + 1 < cnt);
    int y0 = 2 * rp;

    float a0[20], a1[20];
    #pragma unroll
    for (int u = 0; u < 20; u++) { a0[u] = 0.f; a1[u] = 0.f; }

    #pragma unroll 3
    for (int c = 0; c < 51; c++) {
        float2 wp2 = *(const float2*)&Wt[c*52 + l0];
        const float4* xr = (const float4*)&Xs[c*100 + y0*10];
        #pragma unroll
        for (int q = 0; q < 5; q++) {
            float4 xv = xr[q];
            a0[4*q+0] = fmaf(wp2.x, xv.x, a0[4*q+0]);
            a0[4*q+1] = fmaf(wp2.x, xv.y, a0[4*q+1]);
            a0[4*q+2] = fmaf(wp2.x, xv.z, a0[4*q+2]);
            a0[4*q+3] = fmaf(wp2.x, xv.w, a0[4*q+3]);
            a1[4*q+0] = fmaf(wp2.y, xv.x, a1[4*q+0]);
            a1[4*q+1] = fmaf(wp2.y, xv.y, a1[4*q+1]);
            a1[4*q+2] = fmaf(wp2.y, xv.z, a1[4*q+2]);
            a1[4*q+3] = fmaf(wp2.y, xv.w, a1[4*q+3]);
        }
    }

    #pragma unroll
    for (int s = 0; s < 2; s++) {
        if (s == 1 && !v1) break;
        int l = l0 + s;
        float* a = (s == 0) ? a0 : a1;
        int jj = s_j[l], cc = s_cc[l];
        float wj = Wt[jj*52 + l];
        const float* gs = g_h3 + ((size_t)b*255 + cc)*100 + y0*10;
        const float* xj = &Xs[jj*100 + y0*10];
        #pragma unroll
        for (int u = 0; u < 20; u++)
            a[u] = fmaf(wj, gs[u] - xj[u], a[u]);
        float bv = s_b[l];
        float* op = &g_h4[((size_t)b*515 + s_g[l])*25 + rp*5];
        #pragma unroll
        for (int p = 0; p < 5; p++) {
            float v = fmaxf(fmaxf(a[2*p], a[2*p+1]), fmaxf(a[10+2*p], a[10+2*p+1]));
            op[p] = fmaxf(v + bv, 0.f);
        }
    }
}

// =======================================================================
// oo v3: split-K GEMM. grid (8 = 4ks x 2oh, 64 b), 128 threads.
// Block: 50 o x 25 p over K-slice (~129). Thread tile 2o x 5p, c-vec4.
// Writes partials to g_part (bias folded into ks=0).
// =======================================================================
__global__ __launch_bounds__(128) void k_oo(const float* __restrict__ ow,
                                            const float* __restrict__ ob) {
    __shared__ __align__(16) float Xs[25*132];   // [p][cc]
    __shared__ __align__(16) float Ws[50*132];   // [ol][cc]
    int bx = blockIdx.x, b = blockIdx.y, tid = threadIdx.x;
    int ks = bx & 3, oh = bx >> 2;
    int c0 = ks * 129;
    int clen = (ks == 3) ? 128 : 129;
    int obase = oh * 50;

    // zero pads
    for (int i = tid; i < 25*132; i += 128) Xs[i] = 0.f;
    for (int i = tid; i < 50*132; i += 128) Ws[i] = 0.f;
    __syncthreads();
    // X: coalesced LDG, transposed STS  (g_h4[b, c0+cc, p] -> Xs[p][cc])
    for (int i = tid; i < clen*25; i += 128) {
        int cc = i / 25, p = i % 25;
        Xs[p*132 + cc] = g_h4[(size_t)b*12875 + (size_t)c0*25 + i];
    }
    // W rows
    for (int i = tid; i < 50*clen; i += 128) {
        int ol = i / clen, cc = i % clen;
        Ws[ol*132 + cc] = ow[(size_t)(obase + ol)*515 + c0 + cc];
    }
    __syncthreads();

    if (tid >= 125) return;
    int ot = tid / 5, pt = tid % 5;
    int o0 = ot * 2;
    float accA[5] = {0,0,0,0,0};
    float accB[5] = {0,0,0,0,0};
    const float* wp0 = &Ws[o0*132];
    const float* wp1 = wp0 + 132;
    const float* xp0 = &Xs[pt*132];

    #pragma unroll 3
    for (int c4 = 0; c4 < 132; c4 += 4) {
        float4 w0 = *(const float4*)&wp0[c4];
        float4 w1 = *(const float4*)&wp1[c4];
        float4 xv[5];
        #pragma unroll
        for (int kk = 0; kk < 5; kk++)
            xv[kk] = *(const float4*)&xp0[kk*5*132 + c4];
        #pragma unroll
        for (int kk = 0; kk < 5; kk++) {
            accA[kk] = fmaf(w0.x, xv[kk].x, accA[kk]);
            accA[kk] = fmaf(w0.y, xv[kk].y, accA[kk]);
            accA[kk] = fmaf(w0.z, xv[kk].z, accA[kk]);
            accA[kk] = fmaf(w0.w, xv[kk].w, accA[kk]);
            accB[kk] = fmaf(w1.x, xv[kk].x, accB[kk]);
            accB[kk] = fmaf(w1.y, xv[kk].y, accB[kk]);
            accB[kk] = fmaf(w1.z, xv[kk].z, accB[kk]);
            accB[kk] = fmaf(w1.w, xv[kk].w, accB[kk]);
        }
    }

    float bias0 = 0.f, bias1 = 0.f;
    if (ks == 0) { bias0 = __ldg(&ob[obase + o0]); bias1 = __ldg(&ob[obase + o0 + 1]); }
    float* op0 = &g_part[(((size_t)ks*64 + b)*100 + obase + o0)*25];
    float* op1 = op0 + 25;
    #pragma unroll
    for (int kk = 0; kk < 5; kk++) {
        int p = pt + 5*kk;
        op0[p] = accA[kk] + bias0;
        op1[p] = accB[kk] + bias1;
    }
}

// =======================================================================
// reduce oo partials + relu -> g_h5
// =======================================================================
__global__ __launch_bounds__(256) void k_red() {
    int idx = blockIdx.x*256 + threadIdx.x;   // 160000 total
    float v = g_part[idx] + g_part[160000 + idx]
            + g_part[320000 + idx] + g_part[480000 + idx];
    g_h5[idx] = fmaxf(v, 0.f);
}

// =======================================================================
// fc1: [64,2500]x[2500,120] -> g_f1 [64,120] (+bias+relu).
// grid (15 o-tiles, 8 b-tiles), 256 threads, in-block split-K(4).
// =======================================================================
__global__ __launch_bounds__(256) void k_fc1(const float* __restrict__ w1,
                                             const float* __restrict__ b1) {
    __shared__ __align__(16) float Xs[8*260];
    __shared__ __align__(16) float Ws2[8*260];
    __shared__ float s_red[256];
    int o0 = blockIdx.x * 8, b0 = blockIdx.y * 8, tid = threadIdx.x;
    int oi = tid & 7, bi = (tid >> 3) & 7, ksl = tid >> 6;

    float acc = 0.f;
    for (int ch = 0; ch < 10; ch++) {
        int cb = ch * 256;
        __syncthreads();
        for (int i = tid; i < 2048; i += 256) {
            int row = i >> 8, cc = i & 255;
            int c = cb + cc;
            Xs[row*260 + cc]  = (c < 2500) ? g_h5[(size_t)(b0+row)*2500 + c] : 0.f;
            Ws2[row*260 + cc] = (c < 2500) ? w1[(size_t)(o0+row)*2500 + c] : 0.f;
        }
        __syncthreads();
        const float4* xp = (const float4*)&Xs[bi*260 + ksl*64];
        const float4* wp = (const float4*)&Ws2[oi*260 + ksl*64];
        #pragma unroll
        for (int q = 0; q < 16; q++) {
            float4 xv = xp[q], wv = wp[q];
            acc = fmaf(wv.x, xv.x, acc);
            acc = fmaf(wv.y, xv.y, acc);
            acc = fmaf(wv.z, xv.z, acc);
            acc = fmaf(wv.w, xv.w, acc);
        }
    }
    __syncthreads();
    s_red[tid] = acc;
    __syncthreads();
    if (tid < 64) {
        float s = s_red[tid] + s_red[tid+64] + s_red[tid+128] + s_red[tid+192];
        int o = o0 + (tid & 7), bb = b0 + (tid >> 3);
        g_f1[bb*120 + o] = fmaxf(s + __ldg(&b1[o]), 0.f);
    }
}

// =======================================================================
// fc2 + fc3: [64,120] -> 84 -> 10
// =======================================================================
__global__ __launch_bounds__(128) void k_fc23(
    const float* __restrict__ w2, const float* __restrict__ b2,
    const float* __restrict__ w3, const float* __restrict__ b3,
    float* __restrict__ out) {
    __shared__ __align__(16) float sf1[120];
    __shared__ __align__(16) float sf2[84];
    int b = blockIdx.x, tid = threadIdx.x;
    if (tid < 120) sf1[tid] = g_f1[b*120 + tid];
    __syncthreads();
    if (tid < 84) {
        const float4* wp = (const float4*)(w2 + tid*120);
        const float4* xp = (const float4*)sf1;
        float s = 0.f;
        #pragma unroll
        for (int q = 0; q < 30; q++) {
            float4 wv = wp[q], xv = xp[q];
            s = fmaf(wv.x, xv.x, s); s = fmaf(wv.y, xv.y, s);
            s = fmaf(wv.z, xv.z, s); s = fmaf(wv.w, xv.w, s);
        }
        sf2[tid] = fmaxf(s + b2[tid], 0.f);
    }
    __syncthreads();
    if (tid < 10) {
        const float4* wp = (const float4*)(w3 + tid*84);
        const float4* xp = (const float4*)sf2;
        float s = 0.f;
        #pragma unroll
        for (int q = 0; q < 21; q++) {
            float4 wv = wp[q], xv = xp[q];
            s = fmaf(wv.x, xv.x, s); s = fmaf(wv.y, xv.y, s);
            s = fmaf(wv.z, xv.z, s); s = fmaf(wv.w, xv.w, s);
        }
        out[b*10 + tid] = s + b3[tid];
    }
}

// ---------------- launch ----------------
extern "C" void kernel_launch(void* const* d_in, const int* in_sizes, int n_in,
                              void* d_out, int out_size) {
    const float* x      = (const float*)d_in[0];
    const float* dw1_w  = (const float*)d_in[1];
    const float* dw1_b  = (const float*)d_in[2];
    const float* pc1_w  = (const float*)d_in[3];
    const float* pc1_b  = (const float*)d_in[4];
    const float* dw2_w  = (const float*)d_in[5];
    const float* dw2_b  = (const float*)d_in[6];
    const float* pc2_w  = (const float*)d_in[7];
    const float* pc2_b  = (const float*)d_in[8];
    const float* oo_w   = (const float*)d_in[9];
    const float* oo_b   = (const float*)d_in[10];
    const float* fc1_w  = (const float*)d_in[11];
    const float* fc1_b  = (const float*)d_in[12];
    const float* fc2_w  = (const float*)d_in[13];
    const float* fc2_b  = (const float*)d_in[14];
    const float* fc3_w  = (const float*)d_in[15];
    const float* fc3_b  = (const float*)d_in[16];
    float* out = (float*)d_out;

    static bool attr_done = false;
    const int fuse1_smem = (3168 + 14112 + 450 + 18 + 153 + 51 + 153) * 4 + 16;
    if (!attr_done) {
        cudaFuncSetAttribute(k_fuse1, cudaFuncAttributeMaxDynamicSharedMemorySize, fuse1_smem);
        attr_done = true;
    }

    k_fuse1<<<64, 256, fuse1_smem>>>(x, dw1_w, dw1_b, pc1_w, pc1_b);
    k_dw2<<<dim3(10, 64), 256>>>(dw2_w, dw2_b);
    k_pc2<<<dim3(11, 64), 160>>>(pc2_w, pc2_b);
    k_oo<<<dim3(8, 64), 128>>>(oo_w, oo_b);
    k_red<<<625, 256>>>();
    k_fc1<<<dim3(15, 8), 256>>>(fc1_w, fc1_b);
    k_fc23<<<64, 128>>>(fc2_w, fc2_b, fc3_w, fc3_b, out);
}

// round 4
// speedup vs baseline: 2.2578x; 1.1289x over previous
#include <cuda_runtime.h>

// ---------------- scratch (device globals; no allocation) ----------------
__device__ __align__(16) float g_h2[64*51*14*14];    // pool1 out [64,51,14,14]
__device__ __align__(16) float g_h3[64*255*10*10];   // dw2 out   [64,255,10,10]
__device__ __align__(16) float g_h4[64*515*25];      // pool2 out [64,515,5,5]
__device__ __align__(16) float g_part[8*64*100*25];  // oo split-K partials
__device__ __align__(16) float g_h5[64*100*25];      // oo out (post relu)
__device__ __align__(16) float g_f1[64*120];         // fc1 out

// =======================================================================
// fuse1: dw1 + pc1 + relu + maxpool, one block per batch image, 512 thr.
// =======================================================================
__global__ __launch_bounds__(512) void k_fuse1(
    const float* __restrict__ x, const float* __restrict__ dw1w,
    const float* __restrict__ dw1b, const float* __restrict__ pc1w,
    const float* __restrict__ pc1b) {
    extern __shared__ float sm[];
    float* xs  = sm;            // 3*32*33 = 3168
    float* h1  = xs + 3168;     // 18*784 = 14112
    float* ws  = h1 + 14112;    // 450
    float* wb  = ws + 450;      // 18
    float* pwv = wb + 18;       // 153
    float* pbs = pwv + 153;     // 51
    int*   sidx = (int*)(pbs + 51); // 51*3

    int b = blockIdx.x, tid = threadIdx.x;

    for (int i = tid; i < 3072; i += 512) {
        int c = i >> 10, r = (i >> 5) & 31, col = i & 31;
        xs[c*1056 + r*33 + col] = x[(size_t)b*3072 + i];
    }
    if (tid < 450) ws[tid] = dw1w[tid];
    if (tid < 18) wb[tid] = dw1b[tid];
    if (tid < 153) pwv[tid] = pc1w[tid];
    if (tid < 51) {
        pbs[tid] = pc1b[tid];
        int g = tid, gi = g, i = 0;
        for (;;) { int cv = (6 - i) + 2 * (5 - i); if (gi < cv) break; gi -= cv; i++; }
        int j, k;
        if (gi < 6 - i) { j = 0; k = i + gi; }
        else { gi -= 6 - i; int pj = 5 - i; j = 1 + gi / pj; k = i + 1 + gi % pj; }
        sidx[g*3+0] = (0==j) ? i*3+0 : k*3+0;
        sidx[g*3+1] = (1==j) ? i*3+1 : k*3+1;
        sidx[g*3+2] = (2==j) ? i*3+2 : k*3+2;
    }
    __syncthreads();

    // dw1: tasks = (o, py, quarter) = 18*28*4 = 2016; each computes 7 px.
    for (int t = tid; t < 2016; t += 512) {
        int o = t / 112, r = t % 112, py = r / 4, q = r % 4, x0 = q * 7;
        int c = o / 6;
        const float* xb = &xs[c*1056 + py*33 + x0];
        float win[5][11];
        #pragma unroll
        for (int dy = 0; dy < 5; dy++)
            #pragma unroll
            for (int dx = 0; dx < 11; dx++) win[dy][dx] = xb[dy*33 + dx];
        float bv = wb[o];
        float acc[7];
        #pragma unroll
        for (int u = 0; u < 7; u++) acc[u] = bv;
        #pragma unroll
        for (int dy = 0; dy < 5; dy++)
            #pragma unroll
            for (int dx = 0; dx < 5; dx++) {
                float wv = ws[o*25 + dy*5 + dx];
                #pragma unroll
                for (int u = 0; u < 7; u++) acc[u] = fmaf(win[dy][dx+u], wv, acc[u]);
            }
        #pragma unroll
        for (int u = 0; u < 7; u++) h1[o*784 + py*28 + x0 + u] = acc[u];
    }
    __syncthreads();

    // pc1 + pool: tasks = (g, qy, qp) = 51*14*7 = 4998; each -> 2 outputs.
    for (int t = tid; t < 4998; t += 512) {
        int g = t / 98, r = t % 98, qy = r / 7, qp = r % 7;
        float w0 = pwv[g*3], w1 = pwv[g*3+1], w2 = pwv[g*3+2];
        int s0 = sidx[g*3], s1 = sidx[g*3+1], s2 = sidx[g*3+2];
        float v[2][4];
        #pragma unroll
        for (int dy = 0; dy < 2; dy++) {
            int base = (2*qy + dy)*28 + 4*qp;
            float2 a0 = *(const float2*)&h1[s0*784 + base];
            float2 a0b = *(const float2*)&h1[s0*784 + base + 2];
            float2 a1 = *(const float2*)&h1[s1*784 + base];
            float2 a1b = *(const float2*)&h1[s1*784 + base + 2];
            float2 a2 = *(const float2*)&h1[s2*784 + base];
            float2 a2b = *(const float2*)&h1[s2*784 + base + 2];
            v[dy][0] = fmaf(w0, a0.x,  fmaf(w1, a1.x,  w2*a2.x));
            v[dy][1] = fmaf(w0, a0.y,  fmaf(w1, a1.y,  w2*a2.y));
            v[dy][2] = fmaf(w0, a0b.x, fmaf(w1, a1b.x, w2*a2b.x));
            v[dy][3] = fmaf(w0, a0b.y, fmaf(w1, a1b.y, w2*a2b.y));
        }
        float bv = pbs[g];
        float o0 = fmaxf(fmaxf(v[0][0], v[0][1]), fmaxf(v[1][0], v[1][1]));
        float o1 = fmaxf(fmaxf(v[0][2], v[0][3]), fmaxf(v[1][2], v[1][3]));
        float* op = &g_h2[((size_t)b*51 + g)*196 + qy*14 + 2*qp];
        op[0] = fmaxf(o0 + bv, 0.f);
        op[1] = fmaxf(o1 + bv, 0.f);
    }
}

// =======================================================================
// dw2: [64,51,14,14] -> [64,255,10,10].
// =======================================================================
__global__ __launch_bounds__(256) void k_dw2(const float* __restrict__ w,
                                             const float* __restrict__ bias) {
    __shared__ float xs[7*196];
    int bx = blockIdx.x, b = blockIdx.y, tid = threadIdx.x;
    int t0 = bx * 256;
    int c0 = t0 / 50;
    int c1 = min((t0 + 255) / 50, 50);
    int nch = c1 - c0 + 1;
    for (int i = tid; i < nch*196; i += 256)
        xs[i] = g_h2[((size_t)b*51 + c0)*196 + i];
    __syncthreads();

    int t = t0 + tid;
    if (t >= 2550) return;
    int o = t / 10, py = t % 10;
    int cl = o / 5 - c0;
    float wr[25];
    #pragma unroll
    for (int i = 0; i < 25; i++) wr[i] = __ldg(&w[o*25 + i]);
    float bv = __ldg(&bias[o]);
    const float* ib = &xs[cl*196 + py*14];
    float* outp = &g_h3[((size_t)b*255 + o)*100 + py*10];
    #pragma unroll
    for (int h = 0; h < 2; h++) {
        int px0 = h * 5;
        float win[5][9];
        #pragma unroll
        for (int dy = 0; dy < 5; dy++)
            #pragma unroll
            for (int dx = 0; dx < 9; dx++) win[dy][dx] = ib[dy*14 + px0 + dx];
        float acc[5] = {bv, bv, bv, bv, bv};
        #pragma unroll
        for (int dy = 0; dy < 5; dy++)
            #pragma unroll
            for (int dx = 0; dx < 5; dx++) {
                float wv = wr[dy*5 + dx];
                #pragma unroll
                for (int u = 0; u < 5; u++) acc[u] = fmaf(win[dy][dx+u], wv, acc[u]);
            }
        #pragma unroll
        for (int u = 0; u < 5; u++) outp[px0 + u] = acc[u];
    }
}

// =======================================================================
// pc2 + relu + maxpool.
// =======================================================================
__device__ __constant__ int c_bk[11]   = {0,1,2,2,3,3,3,4,4,4,4};
__device__ __constant__ int c_bt[11]   = {0,0,0,52,0,52,104,0,52,104,156};
__device__ __constant__ int c_bc[11]   = {1,52,52,51,52,52,50,52,52,52,49};
__device__ __constant__ int c_base[5]  = {0,205,359,462,514};

__global__ __launch_bounds__(160) void k_pc2(const float* __restrict__ pw,
                                             const float* __restrict__ pb) {
    __shared__ __align__(16) float Xs[5100];
    __shared__ __align__(16) float Wt[51*52];
    __shared__ int   s_g[52], s_cc[52], s_j[52];
    __shared__ float s_b[52];
    int blk = blockIdx.x, b = blockIdx.y, tid = threadIdx.x;
    int k = c_bk[blk], ts = c_bt[blk], cnt = c_bc[blk];

    const float* xsrc = g_h3 + ((size_t)b*255 + k*51)*100;
    for (int i = tid; i < 5100; i += 160) Xs[i] = xsrc[i];
    if (tid < cnt) {
        int t = ts + tid;
        int i, j;
        if (t <= k) { i = t; j = 0; }
        else { int r = t - k - 1; i = r % k; j = 1 + r / k; }
        int g;
        if (j == 0) g = c_base[i] + (k - i);
        else        g = c_base[i] + (5 - i) + (j - 1)*(4 - i) + (k - i - 1);
        s_g[tid] = g; s_cc[tid] = i*51 + j; s_j[tid] = j; s_b[tid] = pb[g];
    }
    __syncthreads();
    for (int i = tid; i < cnt*51; i += 160) {
        int l = i / 51, c = i % 51;
        Wt[c*52 + l] = pw[s_g[l]*51 + c];
    }
    __syncthreads();

    int gt = tid / 5, rp = tid % 5;
    int l0 = gt * 2;
    if (tid >= 130 || l0 >= cnt) return;
    bool v1 = (l0 + 1 < cnt);
    int y0 = 2 * rp;

    float a0[20], a1[20];
    #pragma unroll
    for (int u = 0; u < 20; u++) { a0[u] = 0.f; a1[u] = 0.f; }

    #pragma unroll 3
    for (int c = 0; c < 51; c++) {
        float2 wp2 = *(const float2*)&Wt[c*52 + l0];
        const float4* xr = (const float4*)&Xs[c*100 + y0*10];
        #pragma unroll
        for (int q = 0; q < 5; q++) {
            float4 xv = xr[q];
            a0[4*q+0] = fmaf(wp2.x, xv.x, a0[4*q+0]);
            a0[4*q+1] = fmaf(wp2.x, xv.y, a0[4*q+1]);
            a0[4*q+2] = fmaf(wp2.x, xv.z, a0[4*q+2]);
            a0[4*q+3] = fmaf(wp2.x, xv.w, a0[4*q+3]);
            a1[4*q+0] = fmaf(wp2.y, xv.x, a1[4*q+0]);
            a1[4*q+1] = fmaf(wp2.y, xv.y, a1[4*q+1]);
            a1[4*q+2] = fmaf(wp2.y, xv.z, a1[4*q+2]);
            a1[4*q+3] = fmaf(wp2.y, xv.w, a1[4*q+3]);
        }
    }

    #pragma unroll
    for (int s = 0; s < 2; s++) {
        if (s == 1 && !v1) break;
        int l = l0 + s;
        float* a = (s == 0) ? a0 : a1;
        int jj = s_j[l], cc = s_cc[l];
        float wj = Wt[jj*52 + l];
        const float* gs = g_h3 + ((size_t)b*255 + cc)*100 + y0*10;
        const float* xj = &Xs[jj*100 + y0*10];
        #pragma unroll
        for (int u = 0; u < 20; u++)
            a[u] = fmaf(wj, gs[u] - xj[u], a[u]);
        float bv = s_b[l];
        float* op = &g_h4[((size_t)b*515 + s_g[l])*25 + rp*5];
        #pragma unroll
        for (int p = 0; p < 5; p++) {
            float v = fmaxf(fmaxf(a[2*p], a[2*p+1]), fmaxf(a[10+2*p], a[10+2*p+1]));
            op[p] = fmaxf(v + bv, 0.f);
        }
    }
}

// =======================================================================
// oo v4: 8-way split-K GEMM. grid (16 = 8ks x 2oh, 64 b), 128 threads.
// Division-free staging, constant stride 68, fully unrolled inner loop.
// =======================================================================
__global__ __launch_bounds__(128) void k_oo(const float* __restrict__ ow,
                                            const float* __restrict__ ob) {
    __shared__ __align__(16) float Xs[25*68];   // [p][cc]
    __shared__ __align__(16) float Ws[50*68];   // [ol][cc]
    int bx = blockIdx.x, b = blockIdx.y, tid = threadIdx.x;
    int ks = bx >> 1, oh = bx & 1;
    int c0 = ks * 65;
    int clen = (ks == 7) ? 60 : 65;
    int obase = oh * 50;

    for (int i = tid; i < 25*68; i += 128) Xs[i] = 0.f;
    __syncthreads();
    // X: coalesced LDG, transposed STS (g_h4[b, c0+cc, p] -> Xs[p][cc])
    for (int i = tid; i < clen*25; i += 128) {
        int cc = i / 25, p = i % 25;                 // const divisors
        Xs[p*68 + cc] = g_h4[(size_t)b*12875 + c0*25 + i];
    }
    // W rows, padded with zeros (const divisor 68)
    for (int i = tid; i < 50*68; i += 128) {
        int ol = i / 68, cc = i - ol*68;
        Ws[i] = (cc < clen) ? ow[(size_t)(obase + ol)*515 + c0 + cc] : 0.f;
    }
    __syncthreads();

    if (tid >= 125) return;
    int ot = tid / 5, pt = tid % 5;
    int o0 = ot * 2;
    float accA[5] = {0,0,0,0,0};
    float accB[5] = {0,0,0,0,0};
    const float* wp0 = &Ws[o0*68];
    const float* wp1 = wp0 + 68;
    const float* xp0 = &Xs[pt*68];

    #pragma unroll
    for (int c4 = 0; c4 < 68; c4 += 4) {
        float4 w0 = *(const float4*)&wp0[c4];
        float4 w1 = *(const float4*)&wp1[c4];
        float4 xv[5];
        #pragma unroll
        for (int kk = 0; kk < 5; kk++)
            xv[kk] = *(const float4*)&xp0[kk*5*68 + c4];
        #pragma unroll
        for (int kk = 0; kk < 5; kk++) {
            accA[kk] = fmaf(w0.x, xv[kk].x, accA[kk]);
            accA[kk] = fmaf(w0.y, xv[kk].y, accA[kk]);
            accA[kk] = fmaf(w0.z, xv[kk].z, accA[kk]);
            accA[kk] = fmaf(w0.w, xv[kk].w, accA[kk]);
            accB[kk] = fmaf(w1.x, xv[kk].x, accB[kk]);
            accB[kk] = fmaf(w1.y, xv[kk].y, accB[kk]);
            accB[kk] = fmaf(w1.z, xv[kk].z, accB[kk]);
            accB[kk] = fmaf(w1.w, xv[kk].w, accB[kk]);
        }
    }

    float bias0 = 0.f, bias1 = 0.f;
    if (ks == 0) { bias0 = __ldg(&ob[obase + o0]); bias1 = __ldg(&ob[obase + o0 + 1]); }
    float* op0 = &g_part[(((size_t)ks*64 + b)*100 + obase + o0)*25];
    float* op1 = op0 + 25;
    #pragma unroll
    for (int kk = 0; kk < 5; kk++) {
        int p = pt + 5*kk;
        op0[p] = accA[kk] + bias0;
        op1[p] = accB[kk] + bias1;
    }
}

// =======================================================================
// reduce oo partials (8-way) + relu -> g_h5, float4
// =======================================================================
__global__ __launch_bounds__(256) void k_red() {
    int idx = blockIdx.x*256 + threadIdx.x;     // 40000 float4 total
    if (idx >= 40000) return;
    const float4* gp = (const float4*)g_part;
    float4 v = gp[idx];
    #pragma unroll
    for (int s = 1; s < 8; s++) {
        float4 u = gp[s*40000 + idx];
        v.x += u.x; v.y += u.y; v.z += u.z; v.w += u.w;
    }
    ((float4*)g_h5)[idx] = make_float4(fmaxf(v.x,0.f), fmaxf(v.y,0.f),
                                       fmaxf(v.z,0.f), fmaxf(v.w,0.f));
}

// =======================================================================
// fc1: [64,2500]x[2500,120] -> g_f1 [64,120] (+bias+relu).
// grid (15 o-tiles, 8 b-tiles), 256 threads, split-K(4), double-buffered.
// =======================================================================
__global__ __launch_bounds__(256) void k_fc1(const float* __restrict__ w1,
                                             const float* __restrict__ b1) {
    __shared__ __align__(16) float Xs[2][8*260];
    __shared__ __align__(16) float Ws2[2][8*260];
    __shared__ float s_red[256];
    int o0 = blockIdx.x * 8, b0 = blockIdx.y * 8, tid = threadIdx.x;
    int oi = tid & 7, bi = (tid >> 3) & 7, ksl = tid >> 6;
    int row = tid >> 8;  (void)row;

    // preload chunk 0 (no tail: 256 < 2500)
    #pragma unroll
    for (int u = 0; u < 8; u++) {
        int i = tid + u*256;
        int rw = i >> 8, cc = i & 255;
        Xs[0][rw*260 + cc]  = g_h5[(size_t)(b0+rw)*2500 + cc];
        Ws2[0][rw*260 + cc] = w1[(size_t)(o0+rw)*2500 + cc];
    }
    __syncthreads();

    float acc = 0.f;
    for (int ch = 0; ch < 10; ch++) {
        int cur = ch & 1;
        float xreg[8], wreg[8];
        if (ch < 9) {
            int cb = (ch + 1) * 256;
            #pragma unroll
            for (int u = 0; u < 8; u++) {
                int i = tid + u*256;
                int rw = i >> 8, cc = i & 255;
                int c = cb + cc;
                bool ok = (c < 2500);
                xreg[u] = ok ? g_h5[(size_t)(b0+rw)*2500 + c] : 0.f;
                wreg[u] = ok ? w1[(size_t)(o0+rw)*2500 + c] : 0.f;
            }
        }
        const float4* xp = (const float4*)&Xs[cur][bi*260 + ksl*64];
        const float4* wp = (const float4*)&Ws2[cur][oi*260 + ksl*64];
        #pragma unroll
        for (int q = 0; q < 16; q++) {
            float4 xv = xp[q], wv = wp[q];
            acc = fmaf(wv.x, xv.x, acc);
            acc = fmaf(wv.y, xv.y, acc);
            acc = fmaf(wv.z, xv.z, acc);
            acc = fmaf(wv.w, xv.w, acc);
        }
        if (ch < 9) {
            #pragma unroll
            for (int u = 0; u < 8; u++) {
                int i = tid + u*256;
                int rw = i >> 8, cc = i & 255;
                Xs[1-cur][rw*260 + cc]  = xreg[u];
                Ws2[1-cur][rw*260 + cc] = wreg[u];
            }
        }
        __syncthreads();
    }
    s_red[tid] = acc;
    __syncthreads();
    if (tid < 64) {
        float s = s_red[tid] + s_red[tid+64] + s_red[tid+128] + s_red[tid+192];
        int o = o0 + (tid & 7), bb = b0 + (tid >> 3);
        g_f1[bb*120 + o] = fmaxf(s + __ldg(&b1[o]), 0.f);
    }
}

// =======================================================================
// fc2 + fc3: [64,120] -> 84 -> 10
// =======================================================================
__global__ __launch_bounds__(128) void k_fc23(
    const float* __restrict__ w2, const float* __restrict__ b2,
    const float* __restrict__ w3, const float* __restrict__ b3,
    float* __restrict__ out) {
    __shared__ __align__(16) float sf1[120];
    __shared__ __align__(16) float sf2[84];
    int b = blockIdx.x, tid = threadIdx.x;
    if (tid < 120) sf1[tid] = g_f1[b*120 + tid];
    __syncthreads();
    if (tid < 84) {
        const float4* wp = (const float4*)(w2 + tid*120);
        const float4* xp = (const float4*)sf1;
        float s = 0.f;
        #pragma unroll
        for (int q = 0; q < 30; q++) {
            float4 wv = wp[q], xv = xp[q];
            s = fmaf(wv.x, xv.x, s); s = fmaf(wv.y, xv.y, s);
            s = fmaf(wv.z, xv.z, s); s = fmaf(wv.w, xv.w, s);
        }
        sf2[tid] = fmaxf(s + b2[tid], 0.f);
    }
    __syncthreads();
    if (tid < 10) {
        const float4* wp = (const float4*)(w3 + tid*84);
        const float4* xp = (const float4*)sf2;
        float s = 0.f;
        #pragma unroll
        for (int q = 0; q < 21; q++) {
            float4 wv = wp[q], xv = xp[q];
            s = fmaf(wv.x, xv.x, s); s = fmaf(wv.y, xv.y, s);
            s = fmaf(wv.z, xv.z, s); s = fmaf(wv.w, xv.w, s);
        }
        out[b*10 + tid] = s + b3[tid];
    }
}

// ---------------- launch ----------------
extern "C" void kernel_launch(void* const* d_in, const int* in_sizes, int n_in,
                              void* d_out, int out_size) {
    const float* x      = (const float*)d_in[0];
    const float* dw1_w  = (const float*)d_in[1];
    const float* dw1_b  = (const float*)d_in[2];
    const float* pc1_w  = (const float*)d_in[3];
    const float* pc1_b  = (const float*)d_in[4];
    const float* dw2_w  = (const float*)d_in[5];
    const float* dw2_b  = (const float*)d_in[6];
    const float* pc2_w  = (const float*)d_in[7];
    const float* pc2_b  = (const float*)d_in[8];
    const float* oo_w   = (const float*)d_in[9];
    const float* oo_b   = (const float*)d_in[10];
    const float* fc1_w  = (const float*)d_in[11];
    const float* fc1_b  = (const float*)d_in[12];
    const float* fc2_w  = (const float*)d_in[13];
    const float* fc2_b  = (const float*)d_in[14];
    const float* fc3_w  = (const float*)d_in[15];
    const float* fc3_b  = (const float*)d_in[16];
    float* out = (float*)d_out;

    static bool attr_done = false;
    const int fuse1_smem = (3168 + 14112 + 450 + 18 + 153 + 51 + 153) * 4 + 16;
    if (!attr_done) {
        cudaFuncSetAttribute(k_fuse1, cudaFuncAttributeMaxDynamicSharedMemorySize, fuse1_smem);
        attr_done = true;
    }

    k_fuse1<<<64, 512, fuse1_smem>>>(x, dw1_w, dw1_b, pc1_w, pc1_b);
    k_dw2<<<dim3(10, 64), 256>>>(dw2_w, dw2_b);
    k_pc2<<<dim3(11, 64), 160>>>(pc2_w, pc2_b);
    k_oo<<<dim3(16, 64), 128>>>(oo_w, oo_b);
    k_red<<<157, 256>>>();
    k_fc1<<<dim3(15, 8), 256>>>(fc1_w, fc1_b);
    k_fc23<<<64, 128>>>(fc2_w, fc2_b, fc3_w, fc3_b, out);
}